// round 13
// baseline (speedup 1.0000x reference)
#include <cuda_runtime.h>
#include <cuda_fp16.h>
#include <cstdint>

#define D_IN      128
#define UNITS     128
#define MAX_NODES 100000
#define MAX_EDGES 1600000
#define BIN_CAP   64          // fixed per-row bin capacity (P(deg>=64) ~ 1e-14)
#define XS_STRIDE 136         // halves; 272B row stride -> conflict-free ldmatrix

// ---- device scratch (no runtime allocation allowed) ----
__device__ float              g_xw_f[(size_t)MAX_NODES * UNITS];    // xw fp32 (51.2 MB)
__device__ int                g_cnt[MAX_NODES];
__device__ unsigned long long g_pack[(size_t)MAX_NODES * BIN_CAP];  // fixed-stride bins

// ---- tensor-core primitives ----
__device__ __forceinline__ unsigned smem_u32(const void* p) {
    return (unsigned)__cvta_generic_to_shared(p);
}
__device__ __forceinline__ void ldsm_x4(unsigned addr, unsigned& r0, unsigned& r1,
                                        unsigned& r2, unsigned& r3) {
    asm volatile("ldmatrix.sync.aligned.m8n8.x4.shared.b16 {%0,%1,%2,%3}, [%4];"
                 : "=r"(r0), "=r"(r1), "=r"(r2), "=r"(r3) : "r"(addr));
}
__device__ __forceinline__ void ldsm_x4_t(unsigned addr, unsigned& r0, unsigned& r1,
                                          unsigned& r2, unsigned& r3) {
    asm volatile("ldmatrix.sync.aligned.m8n8.x4.trans.shared.b16 {%0,%1,%2,%3}, [%4];"
                 : "=r"(r0), "=r"(r1), "=r"(r2), "=r"(r3) : "r"(addr));
}
__device__ __forceinline__ void mma_16816(float* c, unsigned a0, unsigned a1, unsigned a2,
                                          unsigned a3, unsigned b0, unsigned b1) {
    asm volatile("mma.sync.aligned.m16n8k16.row.col.f32.f16.f16.f32 "
                 "{%0,%1,%2,%3}, {%4,%5,%6,%7}, {%8,%9}, {%0,%1,%2,%3};"
                 : "+f"(c[0]), "+f"(c[1]), "+f"(c[2]), "+f"(c[3])
                 : "r"(a0), "r"(a1), "r"(a2), "r"(a3), "r"(b0), "r"(b1));
}

// ===========================================================================
// Persistent GEMM: xw = x @ w (fp16 HMMA inputs, fp32 output), 64-row tiles,
// double-buffered x, w staged once per block.
// ===========================================================================
__global__ __launch_bounds__(256, 2) void gemm_kernel(
    const float* __restrict__ x, const float* __restrict__ w,
    int n_rows, int n_tiles)
{
    extern __shared__ __half smh[];
    __half* ws  = smh;                            // [128][XS_STRIDE]
    __half* xs0 = smh + 128 * XS_STRIDE;
    __half* xs1 = smh + (128 + 64) * XS_STRIDE;

    const int tid  = threadIdx.x;
    const int wid  = tid >> 5;
    const int lane = tid & 31;

    {
        const float4* w4 = reinterpret_cast<const float4*>(w);
#pragma unroll
        for (int i = 0; i < 16; i++) {
            const int flat = i * 256 + tid;
            const int k  = flat >> 5;
            const int n4 = flat & 31;
            const float4 wv = w4[flat];
            const __half2 h0 = __floats2half2_rn(wv.x, wv.y);
            const __half2 h1 = __floats2half2_rn(wv.z, wv.w);
            uint2 st;
            st.x = *reinterpret_cast<const unsigned*>(&h0);
            st.y = *reinterpret_cast<const unsigned*>(&h1);
            *reinterpret_cast<uint2*>(&ws[k * XS_STRIDE + n4 * 4]) = st;
        }
    }

    const int wr = wid >> 1;
    const int wc = wid & 1;
    const int r_base = wr * 16;
    const int c_base = wc * 64;
    const unsigned ws_b = smem_u32(ws);
    const int lrow = lane & 15;
    const int lhi  = lane >> 4;

    int tile = blockIdx.x;
    if (tile >= n_tiles) return;

    float4 pf[8];
    {
        const float4* x4 = reinterpret_cast<const float4*>(x + (size_t)tile * 64 * D_IN);
#pragma unroll
        for (int i = 0; i < 8; i++) {
            const int flat = i * 256 + tid;
            const int r    = flat >> 5;
            pf[i] = (tile * 64 + r < n_rows) ? x4[flat] : make_float4(0.f, 0.f, 0.f, 0.f);
        }
    }
    {
        __half* xs = xs0;
#pragma unroll
        for (int i = 0; i < 8; i++) {
            const int flat = i * 256 + tid;
            const int r  = flat >> 5;
            const int k4 = flat & 31;
            const __half2 h0 = __floats2half2_rn(pf[i].x, pf[i].y);
            const __half2 h1 = __floats2half2_rn(pf[i].z, pf[i].w);
            uint2 st;
            st.x = *reinterpret_cast<const unsigned*>(&h0);
            st.y = *reinterpret_cast<const unsigned*>(&h1);
            *reinterpret_cast<uint2*>(&xs[r * XS_STRIDE + k4 * 4]) = st;
        }
    }
    __syncthreads();

    int buf = 0;
    while (true) {
        const int next = tile + gridDim.x;
        const int row0 = tile * 64;

        if (next < n_tiles) {
            const float4* x4 = reinterpret_cast<const float4*>(x + (size_t)next * 64 * D_IN);
#pragma unroll
            for (int i = 0; i < 8; i++) {
                const int flat = i * 256 + tid;
                const int r    = flat >> 5;
                pf[i] = (next * 64 + r < n_rows) ? x4[flat] : make_float4(0.f, 0.f, 0.f, 0.f);
            }
        }

        float acc[8][4];
#pragma unroll
        for (int i = 0; i < 8; i++) { acc[i][0] = acc[i][1] = acc[i][2] = acc[i][3] = 0.f; }
        const unsigned xs_b = smem_u32(buf ? xs1 : xs0);
#pragma unroll
        for (int kt = 0; kt < 8; kt++) {
            const int kb = kt * 16;
            unsigned a0, a1, a2, a3;
            ldsm_x4(xs_b + ((r_base + lrow) * XS_STRIDE + kb + lhi * 8) * 2, a0, a1, a2, a3);
#pragma unroll
            for (int np = 0; np < 4; np++) {
                unsigned b0, b1, b2, b3;
                ldsm_x4_t(ws_b + ((kb + lrow) * XS_STRIDE + c_base + np * 16 + lhi * 8) * 2,
                          b0, b1, b2, b3);
                mma_16816(acc[2 * np],     a0, a1, a2, a3, b0, b1);
                mma_16816(acc[2 * np + 1], a0, a1, a2, a3, b2, b3);
            }
        }

        // epilogue: fp32 stores (float2 per fragment pair)
        {
            const int er = row0 + r_base + (lane >> 2);
            const int ec = c_base + (lane & 3) * 2;
#pragma unroll
            for (int nt = 0; nt < 8; nt++) {
                const int c = ec + nt * 8;
                if (er < n_rows) {
                    *reinterpret_cast<float2*>(&g_xw_f[(size_t)er * UNITS + c]) =
                        make_float2(acc[nt][0], acc[nt][1]);
                }
                if (er + 8 < n_rows) {
                    *reinterpret_cast<float2*>(&g_xw_f[(size_t)(er + 8) * UNITS + c]) =
                        make_float2(acc[nt][2], acc[nt][3]);
                }
            }
        }

        if (next >= n_tiles) break;

        {
            __half* xs = buf ? xs0 : xs1;
#pragma unroll
            for (int i = 0; i < 8; i++) {
                const int flat = i * 256 + tid;
                const int r  = flat >> 5;
                const int k4 = flat & 31;
                const __half2 h0 = __floats2half2_rn(pf[i].x, pf[i].y);
                const __half2 h1 = __floats2half2_rn(pf[i].z, pf[i].w);
                uint2 st;
                st.x = *reinterpret_cast<const unsigned*>(&h0);
                st.y = *reinterpret_cast<const unsigned*>(&h1);
                *reinterpret_cast<uint2*>(&xs[r * XS_STRIDE + k4 * 4]) = st;
            }
        }
        __syncthreads();
        buf ^= 1;
        tile = next;
    }
}

// ===========================================================================
// Fused histogram + bin fill over edge range [e_begin, e_end).
// ===========================================================================
__global__ __launch_bounds__(256) void hist_fill_kernel(
    const int* __restrict__ erow, const int* __restrict__ ecol,
    const float* __restrict__ eval_, int e_begin, int e_end)
{
    const int S  = gridDim.x * blockDim.x;
    const int e0 = e_begin + blockIdx.x * blockDim.x + threadIdx.x;

    int                rows[4];
    unsigned long long pks[4];
    bool               ok[4];
#pragma unroll
    for (int i = 0; i < 4; i++) {
        const int e = e0 + i * S;
        ok[i] = (e < e_end);
        if (ok[i]) {
            rows[i] = erow[e];
            pks[i]  = ((unsigned long long)__float_as_uint(eval_[e]) << 32)
                    | (unsigned int)ecol[e];
        }
    }
    int ranks[4];
#pragma unroll
    for (int i = 0; i < 4; i++)
        if (ok[i]) ranks[i] = atomicAdd(&g_cnt[rows[i]], 1);
#pragma unroll
    for (int i = 0; i < 4; i++)
        if (ok[i] && ranks[i] < BIN_CAP)
            g_pack[(size_t)rows[i] * BIN_CAP + ranks[i]] = pks[i];
}

// ===========================================================================
// Gather v7: fp32 xw, zero conversions. Quarter-warp (8 lanes) per edge;
// each lane reads 4 consecutive float4 (64B) covering 16 columns.
// 2 edges in flight per quarter. ReLU fused, fp32 accumulation.
// ===========================================================================
__global__ __launch_bounds__(256) void gather_kernel(float* __restrict__ out, int n_nodes)
{
    const int wid  = threadIdx.x >> 5;
    const int lane = threadIdx.x & 31;
    const int row  = blockIdx.x * 8 + wid;
    if (row >= n_nodes) return;

    int n = g_cnt[row];
    n = n < BIN_CAP ? n : BIN_CAP;

    const int q  = lane >> 3;   // quarter 0..3 -> which edge of the group
    const int ql = lane & 7;    // 8 slots x 4 float4 = 512B row

    float acc[16];
#pragma unroll
    for (int i = 0; i < 16; i++) acc[i] = 0.f;

    const unsigned long long* pkb = g_pack + (unsigned)row * BIN_CAP;
    const float4* xw4 = reinterpret_cast<const float4*>(g_xw_f);

    for (int j0 = 0; j0 < n; j0 += 32) {
        const int rem = n - j0;
        const int m   = rem < 32 ? rem : 32;
        unsigned long long pk = 0ULL;
        if (lane < m) pk = __ldcg(&pkb[j0 + lane]);

        int t = 0;
        // 2 groups of 4 edges in flight (8 edges per iter)
        for (; t + 8 <= m; t += 8) {
            float4 f[2][4];
            float  vv[2];
#pragma unroll
            for (int g = 0; g < 2; g++) {
                const unsigned long long p = __shfl_sync(0xffffffffu, pk, t + g * 4 + q);
                const unsigned col = (unsigned)(p & 0xffffffffULL);
                vv[g] = __uint_as_float((unsigned)(p >> 32));
                const unsigned off = col * 32u + (unsigned)ql * 4u;
#pragma unroll
                for (int j = 0; j < 4; j++) f[g][j] = __ldcg(xw4 + off + j);
            }
#pragma unroll
            for (int g = 0; g < 2; g++) {
#pragma unroll
                for (int j = 0; j < 4; j++) {
                    acc[j * 4 + 0] = fmaf(vv[g], f[g][j].x, acc[j * 4 + 0]);
                    acc[j * 4 + 1] = fmaf(vv[g], f[g][j].y, acc[j * 4 + 1]);
                    acc[j * 4 + 2] = fmaf(vv[g], f[g][j].z, acc[j * 4 + 2]);
                    acc[j * 4 + 3] = fmaf(vv[g], f[g][j].w, acc[j * 4 + 3]);
                }
            }
        }
        // tail: one group of <=4 edges (idx>=m -> v=0, load harmless)
        for (; t < m; t += 4) {
            const int idx = t + q;
            const unsigned long long p = __shfl_sync(0xffffffffu, pk, idx & 31);
            const float v = (idx < m) ? __uint_as_float((unsigned)(p >> 32)) : 0.f;
            const unsigned col = (unsigned)(p & 0xffffffffULL);
            const unsigned off = col * 32u + (unsigned)ql * 4u;
            float4 f[4];
#pragma unroll
            for (int j = 0; j < 4; j++) f[j] = __ldcg(xw4 + off + j);
#pragma unroll
            for (int j = 0; j < 4; j++) {
                acc[j * 4 + 0] = fmaf(v, f[j].x, acc[j * 4 + 0]);
                acc[j * 4 + 1] = fmaf(v, f[j].y, acc[j * 4 + 1]);
                acc[j * 4 + 2] = fmaf(v, f[j].z, acc[j * 4 + 2]);
                acc[j * 4 + 3] = fmaf(v, f[j].w, acc[j * 4 + 3]);
            }
        }
    }

    // reduce the 4 quarters
#pragma unroll
    for (int i = 0; i < 16; i++) {
        acc[i] += __shfl_down_sync(0xffffffffu, acc[i], 8);
        acc[i] += __shfl_down_sync(0xffffffffu, acc[i], 16);
    }

    if (q == 0) {
        // lane ql owns cols [ql*16, ql*16+16)
        float4* dst = reinterpret_cast<float4*>(out + (size_t)row * UNITS + ql * 16);
#pragma unroll
        for (int j = 0; j < 4; j++) {
            float4 o = make_float4(fmaxf(acc[j * 4 + 0], 0.f), fmaxf(acc[j * 4 + 1], 0.f),
                                   fmaxf(acc[j * 4 + 2], 0.f), fmaxf(acc[j * 4 + 3], 0.f));
            __stcg(&dst[j], o);
        }
    }
}

// ===========================================================================
// kernel_launch: graph-capturable, allocation-free.
// ===========================================================================
extern "C" void kernel_launch(void* const* d_in, const int* in_sizes, int n_in,
                              void* d_out, int out_size)
{
    const float* x     = (const float*)d_in[0];
    const float* w     = (const float*)d_in[1];
    const int*   erow  = (const int*)  d_in[2];
    const int*   ecol  = (const int*)  d_in[3];
    const float* eval_ = (const float*)d_in[4];
    float*       out   = (float*)d_out;

    const int n_nodes = in_sizes[0] / D_IN;
    const int n_edges = in_sizes[2];

    static bool         init_done = false;
    static void*        cnt_ptr   = nullptr;
    static cudaStream_t s2;
    static cudaEvent_t  ev_fork, ev_gemm;
    const int gemm_smem = (128 + 128) * XS_STRIDE * (int)sizeof(__half);  // 69632 B
    if (!init_done) {
        cudaFuncSetAttribute(gemm_kernel,
                             cudaFuncAttributeMaxDynamicSharedMemorySize, gemm_smem);
        cudaGetSymbolAddress(&cnt_ptr, g_cnt);
        cudaStreamCreateWithFlags(&s2, cudaStreamNonBlocking);
        cudaEventCreateWithFlags(&ev_fork, cudaEventDisableTiming);
        cudaEventCreateWithFlags(&ev_gemm, cudaEventDisableTiming);
        init_done = true;
    }

    const int n_tiles   = (n_nodes + 63) / 64;
    const int gemm_grid = 296;

    // Fork: GEMM on s2 overlaps edge prep on stream 0.
    cudaEventRecord(ev_fork, 0);
    cudaStreamWaitEvent(s2, ev_fork, 0);
    gemm_kernel<<<gemm_grid, 256, gemm_smem, s2>>>(x, w, n_nodes, n_tiles);
    cudaEventRecord(ev_gemm, s2);

    // Edge prep on stream 0 (hist_fill split in 2 for profiling alignment).
    cudaMemsetAsync(cnt_ptr, 0, (size_t)n_nodes * sizeof(int), 0);
    const int e_half    = n_edges / 2;
    const int hf_blocks = (e_half + 256 * 4 - 1) / (256 * 4);
    hist_fill_kernel<<<hf_blocks, 256>>>(erow, ecol, eval_, 0, e_half);
    hist_fill_kernel<<<hf_blocks, 256>>>(erow, ecol, eval_, e_half, n_edges);

    // Join: gather needs bins (stream 0) and xw (s2).
    cudaStreamWaitEvent(0, ev_gemm, 0);
    gather_kernel<<<(n_nodes + 7) / 8, 256>>>(out, n_nodes);
}

// round 14
// speedup vs baseline: 1.5751x; 1.5751x over previous
#include <cuda_runtime.h>
#include <cuda_fp16.h>
#include <cstdint>

#define D_IN      128
#define UNITS     128
#define MAX_NODES 100000
#define MAX_EDGES 1600000
#define BIN_CAP   64          // fixed per-row bin capacity (P(deg>=64) ~ 1e-14)
#define XS_STRIDE 136         // halves; 272B row stride -> conflict-free ldmatrix

// ---- device scratch (no runtime allocation allowed) ----
__device__ float              g_xw_f[(size_t)MAX_NODES * UNITS];    // xw fp32 (51.2 MB)
__device__ int                g_cnt[MAX_NODES];
__device__ unsigned long long g_pack[(size_t)MAX_NODES * BIN_CAP];  // fixed-stride bins

// ---- tensor-core primitives ----
__device__ __forceinline__ unsigned smem_u32(const void* p) {
    return (unsigned)__cvta_generic_to_shared(p);
}
__device__ __forceinline__ void ldsm_x4(unsigned addr, unsigned& r0, unsigned& r1,
                                        unsigned& r2, unsigned& r3) {
    asm volatile("ldmatrix.sync.aligned.m8n8.x4.shared.b16 {%0,%1,%2,%3}, [%4];"
                 : "=r"(r0), "=r"(r1), "=r"(r2), "=r"(r3) : "r"(addr));
}
__device__ __forceinline__ void ldsm_x4_t(unsigned addr, unsigned& r0, unsigned& r1,
                                          unsigned& r2, unsigned& r3) {
    asm volatile("ldmatrix.sync.aligned.m8n8.x4.trans.shared.b16 {%0,%1,%2,%3}, [%4];"
                 : "=r"(r0), "=r"(r1), "=r"(r2), "=r"(r3) : "r"(addr));
}
__device__ __forceinline__ void mma_16816(float* c, unsigned a0, unsigned a1, unsigned a2,
                                          unsigned a3, unsigned b0, unsigned b1) {
    asm volatile("mma.sync.aligned.m16n8k16.row.col.f32.f16.f16.f32 "
                 "{%0,%1,%2,%3}, {%4,%5,%6,%7}, {%8,%9}, {%0,%1,%2,%3};"
                 : "+f"(c[0]), "+f"(c[1]), "+f"(c[2]), "+f"(c[3])
                 : "r"(a0), "r"(a1), "r"(a2), "r"(a3), "r"(b0), "r"(b1));
}

// ===========================================================================
// Persistent GEMM: xw = x @ w (fp16 HMMA inputs, fp32 output), 64-row tiles,
// double-buffered x, w staged once per block.
// ===========================================================================
__global__ __launch_bounds__(256, 2) void gemm_kernel(
    const float* __restrict__ x, const float* __restrict__ w,
    int n_rows, int n_tiles)
{
    extern __shared__ __half smh[];
    __half* ws  = smh;                            // [128][XS_STRIDE]
    __half* xs0 = smh + 128 * XS_STRIDE;
    __half* xs1 = smh + (128 + 64) * XS_STRIDE;

    const int tid  = threadIdx.x;
    const int wid  = tid >> 5;
    const int lane = tid & 31;

    {
        const float4* w4 = reinterpret_cast<const float4*>(w);
#pragma unroll
        for (int i = 0; i < 16; i++) {
            const int flat = i * 256 + tid;
            const int k  = flat >> 5;
            const int n4 = flat & 31;
            const float4 wv = w4[flat];
            const __half2 h0 = __floats2half2_rn(wv.x, wv.y);
            const __half2 h1 = __floats2half2_rn(wv.z, wv.w);
            uint2 st;
            st.x = *reinterpret_cast<const unsigned*>(&h0);
            st.y = *reinterpret_cast<const unsigned*>(&h1);
            *reinterpret_cast<uint2*>(&ws[k * XS_STRIDE + n4 * 4]) = st;
        }
    }

    const int wr = wid >> 1;
    const int wc = wid & 1;
    const int r_base = wr * 16;
    const int c_base = wc * 64;
    const unsigned ws_b = smem_u32(ws);
    const int lrow = lane & 15;
    const int lhi  = lane >> 4;

    int tile = blockIdx.x;
    if (tile >= n_tiles) return;

    float4 pf[8];
    {
        const float4* x4 = reinterpret_cast<const float4*>(x + (size_t)tile * 64 * D_IN);
#pragma unroll
        for (int i = 0; i < 8; i++) {
            const int flat = i * 256 + tid;
            const int r    = flat >> 5;
            pf[i] = (tile * 64 + r < n_rows) ? x4[flat] : make_float4(0.f, 0.f, 0.f, 0.f);
        }
    }
    {
        __half* xs = xs0;
#pragma unroll
        for (int i = 0; i < 8; i++) {
            const int flat = i * 256 + tid;
            const int r  = flat >> 5;
            const int k4 = flat & 31;
            const __half2 h0 = __floats2half2_rn(pf[i].x, pf[i].y);
            const __half2 h1 = __floats2half2_rn(pf[i].z, pf[i].w);
            uint2 st;
            st.x = *reinterpret_cast<const unsigned*>(&h0);
            st.y = *reinterpret_cast<const unsigned*>(&h1);
            *reinterpret_cast<uint2*>(&xs[r * XS_STRIDE + k4 * 4]) = st;
        }
    }
    __syncthreads();

    int buf = 0;
    while (true) {
        const int next = tile + gridDim.x;
        const int row0 = tile * 64;

        if (next < n_tiles) {
            const float4* x4 = reinterpret_cast<const float4*>(x + (size_t)next * 64 * D_IN);
#pragma unroll
            for (int i = 0; i < 8; i++) {
                const int flat = i * 256 + tid;
                const int r    = flat >> 5;
                pf[i] = (next * 64 + r < n_rows) ? x4[flat] : make_float4(0.f, 0.f, 0.f, 0.f);
            }
        }

        float acc[8][4];
#pragma unroll
        for (int i = 0; i < 8; i++) { acc[i][0] = acc[i][1] = acc[i][2] = acc[i][3] = 0.f; }
        const unsigned xs_b = smem_u32(buf ? xs1 : xs0);
#pragma unroll
        for (int kt = 0; kt < 8; kt++) {
            const int kb = kt * 16;
            unsigned a0, a1, a2, a3;
            ldsm_x4(xs_b + ((r_base + lrow) * XS_STRIDE + kb + lhi * 8) * 2, a0, a1, a2, a3);
#pragma unroll
            for (int np = 0; np < 4; np++) {
                unsigned b0, b1, b2, b3;
                ldsm_x4_t(ws_b + ((kb + lrow) * XS_STRIDE + c_base + np * 16 + lhi * 8) * 2,
                          b0, b1, b2, b3);
                mma_16816(acc[2 * np],     a0, a1, a2, a3, b0, b1);
                mma_16816(acc[2 * np + 1], a0, a1, a2, a3, b2, b3);
            }
        }

        // epilogue: fp32 stores
        {
            const int er = row0 + r_base + (lane >> 2);
            const int ec = c_base + (lane & 3) * 2;
#pragma unroll
            for (int nt = 0; nt < 8; nt++) {
                const int c = ec + nt * 8;
                if (er < n_rows) {
                    *reinterpret_cast<float2*>(&g_xw_f[(size_t)er * UNITS + c]) =
                        make_float2(acc[nt][0], acc[nt][1]);
                }
                if (er + 8 < n_rows) {
                    *reinterpret_cast<float2*>(&g_xw_f[(size_t)(er + 8) * UNITS + c]) =
                        make_float2(acc[nt][2], acc[nt][3]);
                }
            }
        }

        if (next >= n_tiles) break;

        {
            __half* xs = buf ? xs0 : xs1;
#pragma unroll
            for (int i = 0; i < 8; i++) {
                const int flat = i * 256 + tid;
                const int r  = flat >> 5;
                const int k4 = flat & 31;
                const __half2 h0 = __floats2half2_rn(pf[i].x, pf[i].y);
                const __half2 h1 = __floats2half2_rn(pf[i].z, pf[i].w);
                uint2 st;
                st.x = *reinterpret_cast<const unsigned*>(&h0);
                st.y = *reinterpret_cast<const unsigned*>(&h1);
                *reinterpret_cast<uint2*>(&xs[r * XS_STRIDE + k4 * 4]) = st;
            }
        }
        __syncthreads();
        buf ^= 1;
        tile = next;
    }
}

// ===========================================================================
// Fused histogram + bin fill over edge range [e_begin, e_end).
// ===========================================================================
__global__ __launch_bounds__(256) void hist_fill_kernel(
    const int* __restrict__ erow, const int* __restrict__ ecol,
    const float* __restrict__ eval_, int e_begin, int e_end)
{
    const int S  = gridDim.x * blockDim.x;
    const int e0 = e_begin + blockIdx.x * blockDim.x + threadIdx.x;

    int                rows[4];
    unsigned long long pks[4];
    bool               ok[4];
#pragma unroll
    for (int i = 0; i < 4; i++) {
        const int e = e0 + i * S;
        ok[i] = (e < e_end);
        if (ok[i]) {
            rows[i] = erow[e];
            pks[i]  = ((unsigned long long)__float_as_uint(eval_[e]) << 32)
                    | (unsigned int)ecol[e];
        }
    }
    int ranks[4];
#pragma unroll
    for (int i = 0; i < 4; i++)
        if (ok[i]) ranks[i] = atomicAdd(&g_cnt[rows[i]], 1);
#pragma unroll
    for (int i = 0; i < 4; i++)
        if (ok[i] && ranks[i] < BIN_CAP)
            g_pack[(size_t)rows[i] * BIN_CAP + ranks[i]] = pks[i];
}

// ===========================================================================
// Gather v8: fp32 xw, LINE-COALESCED interleave. Quarter-warp (8 lanes) per
// edge; load j of lane ql hits float4 slot (j*8 + ql): each LDG.128's quarter
// covers exactly one 128B line. 2 edges in flight per quarter. ReLU fused.
// ===========================================================================
__global__ __launch_bounds__(256) void gather_kernel(float* __restrict__ out, int n_nodes)
{
    const int wid  = threadIdx.x >> 5;
    const int lane = threadIdx.x & 31;
    const int row  = blockIdx.x * 8 + wid;
    if (row >= n_nodes) return;

    int n = g_cnt[row];
    n = n < BIN_CAP ? n : BIN_CAP;

    const int q  = lane >> 3;   // quarter 0..3 -> which edge of the group
    const int ql = lane & 7;    // slot within the 128B line

    float acc[16];
#pragma unroll
    for (int i = 0; i < 16; i++) acc[i] = 0.f;

    const unsigned long long* pkb = g_pack + (unsigned)row * BIN_CAP;
    const float4* xw4 = reinterpret_cast<const float4*>(g_xw_f);

    for (int j0 = 0; j0 < n; j0 += 32) {
        const int rem = n - j0;
        const int m   = rem < 32 ? rem : 32;
        unsigned long long pk = 0ULL;
        if (lane < m) pk = __ldcg(&pkb[j0 + lane]);

        int t = 0;
        // 2 groups of 4 edges in flight (8 edges per iter, 8 LDG.128/lane out)
        for (; t + 8 <= m; t += 8) {
            float4 f[2][4];
            float  vv[2];
#pragma unroll
            for (int g = 0; g < 2; g++) {
                const unsigned long long p = __shfl_sync(0xffffffffu, pk, t + g * 4 + q);
                const unsigned col = (unsigned)(p & 0xffffffffULL);
                vv[g] = __uint_as_float((unsigned)(p >> 32));
                const unsigned base = col * 32u + (unsigned)ql;
#pragma unroll
                for (int j = 0; j < 4; j++) f[g][j] = __ldcg(xw4 + base + j * 8u);
            }
#pragma unroll
            for (int g = 0; g < 2; g++) {
#pragma unroll
                for (int j = 0; j < 4; j++) {
                    acc[j * 4 + 0] = fmaf(vv[g], f[g][j].x, acc[j * 4 + 0]);
                    acc[j * 4 + 1] = fmaf(vv[g], f[g][j].y, acc[j * 4 + 1]);
                    acc[j * 4 + 2] = fmaf(vv[g], f[g][j].z, acc[j * 4 + 2]);
                    acc[j * 4 + 3] = fmaf(vv[g], f[g][j].w, acc[j * 4 + 3]);
                }
            }
        }
        // tail: one group of <=4 edges (idx>=m -> v=0, load harmless)
        for (; t < m; t += 4) {
            const int idx = t + q;
            const unsigned long long p = __shfl_sync(0xffffffffu, pk, idx & 31);
            const float v = (idx < m) ? __uint_as_float((unsigned)(p >> 32)) : 0.f;
            const unsigned col = (unsigned)(p & 0xffffffffULL);
            const unsigned base = col * 32u + (unsigned)ql;
            float4 f[4];
#pragma unroll
            for (int j = 0; j < 4; j++) f[j] = __ldcg(xw4 + base + j * 8u);
#pragma unroll
            for (int j = 0; j < 4; j++) {
                acc[j * 4 + 0] = fmaf(v, f[j].x, acc[j * 4 + 0]);
                acc[j * 4 + 1] = fmaf(v, f[j].y, acc[j * 4 + 1]);
                acc[j * 4 + 2] = fmaf(v, f[j].z, acc[j * 4 + 2]);
                acc[j * 4 + 3] = fmaf(v, f[j].w, acc[j * 4 + 3]);
            }
        }
    }

    // reduce the 4 quarters
#pragma unroll
    for (int i = 0; i < 16; i++) {
        acc[i] += __shfl_down_sync(0xffffffffu, acc[i], 8);
        acc[i] += __shfl_down_sync(0xffffffffu, acc[i], 16);
    }

    if (q == 0) {
        // lane ql owns float4 slots {ql, 8+ql, 16+ql, 24+ql} of the output row
        float4* dst = reinterpret_cast<float4*>(out + (size_t)row * UNITS);
#pragma unroll
        for (int j = 0; j < 4; j++) {
            float4 o = make_float4(fmaxf(acc[j * 4 + 0], 0.f), fmaxf(acc[j * 4 + 1], 0.f),
                                   fmaxf(acc[j * 4 + 2], 0.f), fmaxf(acc[j * 4 + 3], 0.f));
            __stcg(&dst[j * 8 + ql], o);
        }
    }
}

// ===========================================================================
// kernel_launch: graph-capturable, allocation-free.
// ===========================================================================
extern "C" void kernel_launch(void* const* d_in, const int* in_sizes, int n_in,
                              void* d_out, int out_size)
{
    const float* x     = (const float*)d_in[0];
    const float* w     = (const float*)d_in[1];
    const int*   erow  = (const int*)  d_in[2];
    const int*   ecol  = (const int*)  d_in[3];
    const float* eval_ = (const float*)d_in[4];
    float*       out   = (float*)d_out;

    const int n_nodes = in_sizes[0] / D_IN;
    const int n_edges = in_sizes[2];

    static bool         init_done = false;
    static void*        cnt_ptr   = nullptr;
    static cudaStream_t s2;
    static cudaEvent_t  ev_fork, ev_gemm;
    const int gemm_smem = (128 + 128) * XS_STRIDE * (int)sizeof(__half);  // 69632 B
    if (!init_done) {
        cudaFuncSetAttribute(gemm_kernel,
                             cudaFuncAttributeMaxDynamicSharedMemorySize, gemm_smem);
        cudaGetSymbolAddress(&cnt_ptr, g_cnt);
        cudaStreamCreateWithFlags(&s2, cudaStreamNonBlocking);
        cudaEventCreateWithFlags(&ev_fork, cudaEventDisableTiming);
        cudaEventCreateWithFlags(&ev_gemm, cudaEventDisableTiming);
        init_done = true;
    }

    const int n_tiles   = (n_nodes + 63) / 64;
    const int gemm_grid = 296;

    // Fork: GEMM on s2 overlaps edge prep on stream 0.
    cudaEventRecord(ev_fork, 0);
    cudaStreamWaitEvent(s2, ev_fork, 0);
    gemm_kernel<<<gemm_grid, 256, gemm_smem, s2>>>(x, w, n_nodes, n_tiles);
    cudaEventRecord(ev_gemm, s2);

    // Edge prep on stream 0 (hist_fill split in 2 for profiling alignment).
    cudaMemsetAsync(cnt_ptr, 0, (size_t)n_nodes * sizeof(int), 0);
    const int e_half    = n_edges / 2;
    const int hf_blocks = (e_half + 256 * 4 - 1) / (256 * 4);
    hist_fill_kernel<<<hf_blocks, 256>>>(erow, ecol, eval_, 0, e_half);
    hist_fill_kernel<<<hf_blocks, 256>>>(erow, ecol, eval_, e_half, n_edges);

    // Join: gather needs bins (stream 0) and xw (s2).
    cudaStreamWaitEvent(0, ev_gemm, 0);
    gather_kernel<<<(n_nodes + 7) / 8, 256>>>(out, n_nodes);
}

// round 15
// speedup vs baseline: 2.4756x; 1.5717x over previous
#include <cuda_runtime.h>
#include <cuda_fp16.h>
#include <cstdint>

#define D_IN      128
#define UNITS     128
#define MAX_NODES 100000
#define MAX_EDGES 1600000
#define BIN_CAP   64          // fixed per-row bin capacity (P(deg>=64) ~ 1e-14)
#define XS_STRIDE 136         // halves; 272B row stride -> conflict-free ldmatrix

// ---- device scratch (no runtime allocation allowed) ----
__device__ uint4              g_xw_h[(size_t)MAX_NODES * 16];       // xw fp16, 128 halves/row
__device__ int                g_cnt[MAX_NODES];
__device__ unsigned long long g_pack[(size_t)MAX_NODES * BIN_CAP];  // fixed-stride bins

// ---- f32x2 packed helpers ----
__device__ __forceinline__ unsigned long long pack2(float lo, float hi) {
    unsigned long long r;
    asm("mov.b64 %0, {%1, %2};" : "=l"(r) : "r"(__float_as_uint(lo)), "r"(__float_as_uint(hi)));
    return r;
}
__device__ __forceinline__ void unpack2(unsigned long long v, float& lo, float& hi) {
    unsigned int a, b;
    asm("mov.b64 {%0, %1}, %2;" : "=r"(a), "=r"(b) : "l"(v));
    lo = __uint_as_float(a);
    hi = __uint_as_float(b);
}
__device__ __forceinline__ void fma2(unsigned long long& d, unsigned long long a, unsigned long long b) {
    asm("fma.rn.f32x2 %0, %1, %2, %0;" : "+l"(d) : "l"(a), "l"(b));
}

// ---- tensor-core primitives ----
__device__ __forceinline__ unsigned smem_u32(const void* p) {
    return (unsigned)__cvta_generic_to_shared(p);
}
__device__ __forceinline__ void ldsm_x4(unsigned addr, unsigned& r0, unsigned& r1,
                                        unsigned& r2, unsigned& r3) {
    asm volatile("ldmatrix.sync.aligned.m8n8.x4.shared.b16 {%0,%1,%2,%3}, [%4];"
                 : "=r"(r0), "=r"(r1), "=r"(r2), "=r"(r3) : "r"(addr));
}
__device__ __forceinline__ void ldsm_x4_t(unsigned addr, unsigned& r0, unsigned& r1,
                                          unsigned& r2, unsigned& r3) {
    asm volatile("ldmatrix.sync.aligned.m8n8.x4.trans.shared.b16 {%0,%1,%2,%3}, [%4];"
                 : "=r"(r0), "=r"(r1), "=r"(r2), "=r"(r3) : "r"(addr));
}
__device__ __forceinline__ void mma_16816(float* c, unsigned a0, unsigned a1, unsigned a2,
                                          unsigned a3, unsigned b0, unsigned b1) {
    asm volatile("mma.sync.aligned.m16n8k16.row.col.f32.f16.f16.f32 "
                 "{%0,%1,%2,%3}, {%4,%5,%6,%7}, {%8,%9}, {%0,%1,%2,%3};"
                 : "+f"(c[0]), "+f"(c[1]), "+f"(c[2]), "+f"(c[3])
                 : "r"(a0), "r"(a1), "r"(a2), "r"(a3), "r"(b0), "r"(b1));
}

// ===========================================================================
// Persistent GEMM: xw = x @ w (fp16 HMMA), 64-row tiles, double-buffered x,
// w staged once per block. fp16 epilogue into g_xw_h.
// ===========================================================================
__global__ __launch_bounds__(256, 2) void gemm_kernel(
    const float* __restrict__ x, const float* __restrict__ w,
    int n_rows, int n_tiles)
{
    extern __shared__ __half smh[];
    __half* ws  = smh;                            // [128][XS_STRIDE]
    __half* xs0 = smh + 128 * XS_STRIDE;
    __half* xs1 = smh + (128 + 64) * XS_STRIDE;

    const int tid  = threadIdx.x;
    const int wid  = tid >> 5;
    const int lane = tid & 31;

    {
        const float4* w4 = reinterpret_cast<const float4*>(w);
#pragma unroll
        for (int i = 0; i < 16; i++) {
            const int flat = i * 256 + tid;
            const int k  = flat >> 5;
            const int n4 = flat & 31;
            const float4 wv = w4[flat];
            const __half2 h0 = __floats2half2_rn(wv.x, wv.y);
            const __half2 h1 = __floats2half2_rn(wv.z, wv.w);
            uint2 st;
            st.x = *reinterpret_cast<const unsigned*>(&h0);
            st.y = *reinterpret_cast<const unsigned*>(&h1);
            *reinterpret_cast<uint2*>(&ws[k * XS_STRIDE + n4 * 4]) = st;
        }
    }

    const int wr = wid >> 1;
    const int wc = wid & 1;
    const int r_base = wr * 16;
    const int c_base = wc * 64;
    const unsigned ws_b = smem_u32(ws);
    const int lrow = lane & 15;
    const int lhi  = lane >> 4;

    int tile = blockIdx.x;
    if (tile >= n_tiles) return;

    float4 pf[8];
    {
        const float4* x4 = reinterpret_cast<const float4*>(x + (size_t)tile * 64 * D_IN);
#pragma unroll
        for (int i = 0; i < 8; i++) {
            const int flat = i * 256 + tid;
            const int r    = flat >> 5;
            pf[i] = (tile * 64 + r < n_rows) ? x4[flat] : make_float4(0.f, 0.f, 0.f, 0.f);
        }
    }
    {
        __half* xs = xs0;
#pragma unroll
        for (int i = 0; i < 8; i++) {
            const int flat = i * 256 + tid;
            const int r  = flat >> 5;
            const int k4 = flat & 31;
            const __half2 h0 = __floats2half2_rn(pf[i].x, pf[i].y);
            const __half2 h1 = __floats2half2_rn(pf[i].z, pf[i].w);
            uint2 st;
            st.x = *reinterpret_cast<const unsigned*>(&h0);
            st.y = *reinterpret_cast<const unsigned*>(&h1);
            *reinterpret_cast<uint2*>(&xs[r * XS_STRIDE + k4 * 4]) = st;
        }
    }
    __syncthreads();

    int buf = 0;
    while (true) {
        const int next = tile + gridDim.x;
        const int row0 = tile * 64;

        if (next < n_tiles) {
            const float4* x4 = reinterpret_cast<const float4*>(x + (size_t)next * 64 * D_IN);
#pragma unroll
            for (int i = 0; i < 8; i++) {
                const int flat = i * 256 + tid;
                const int r    = flat >> 5;
                pf[i] = (next * 64 + r < n_rows) ? x4[flat] : make_float4(0.f, 0.f, 0.f, 0.f);
            }
        }

        float acc[8][4];
#pragma unroll
        for (int i = 0; i < 8; i++) { acc[i][0] = acc[i][1] = acc[i][2] = acc[i][3] = 0.f; }
        const unsigned xs_b = smem_u32(buf ? xs1 : xs0);
#pragma unroll
        for (int kt = 0; kt < 8; kt++) {
            const int kb = kt * 16;
            unsigned a0, a1, a2, a3;
            ldsm_x4(xs_b + ((r_base + lrow) * XS_STRIDE + kb + lhi * 8) * 2, a0, a1, a2, a3);
#pragma unroll
            for (int np = 0; np < 4; np++) {
                unsigned b0, b1, b2, b3;
                ldsm_x4_t(ws_b + ((kb + lrow) * XS_STRIDE + c_base + np * 16 + lhi * 8) * 2,
                          b0, b1, b2, b3);
                mma_16816(acc[2 * np],     a0, a1, a2, a3, b0, b1);
                mma_16816(acc[2 * np + 1], a0, a1, a2, a3, b2, b3);
            }
        }

        {
            __half* xw = reinterpret_cast<__half*>(g_xw_h);
            const int er = row0 + r_base + (lane >> 2);
            const int ec = c_base + (lane & 3) * 2;
#pragma unroll
            for (int nt = 0; nt < 8; nt++) {
                const int c = ec + nt * 8;
                if (er < n_rows) {
                    const __half2 h = __floats2half2_rn(acc[nt][0], acc[nt][1]);
                    *reinterpret_cast<unsigned*>(&xw[(size_t)er * UNITS + c]) =
                        *reinterpret_cast<const unsigned*>(&h);
                }
                if (er + 8 < n_rows) {
                    const __half2 h = __floats2half2_rn(acc[nt][2], acc[nt][3]);
                    *reinterpret_cast<unsigned*>(&xw[(size_t)(er + 8) * UNITS + c]) =
                        *reinterpret_cast<const unsigned*>(&h);
                }
            }
        }

        if (next >= n_tiles) break;

        {
            __half* xs = buf ? xs0 : xs1;
#pragma unroll
            for (int i = 0; i < 8; i++) {
                const int flat = i * 256 + tid;
                const int r  = flat >> 5;
                const int k4 = flat & 31;
                const __half2 h0 = __floats2half2_rn(pf[i].x, pf[i].y);
                const __half2 h1 = __floats2half2_rn(pf[i].z, pf[i].w);
                uint2 st;
                st.x = *reinterpret_cast<const unsigned*>(&h0);
                st.y = *reinterpret_cast<const unsigned*>(&h1);
                *reinterpret_cast<uint2*>(&xs[r * XS_STRIDE + k4 * 4]) = st;
            }
        }
        __syncthreads();
        buf ^= 1;
        tile = next;
    }
}

// ===========================================================================
// Fused histogram + bin fill: 8 independent edges per thread (atomic MLP).
// ===========================================================================
__global__ __launch_bounds__(256) void hist_fill_kernel(
    const int* __restrict__ erow, const int* __restrict__ ecol,
    const float* __restrict__ eval_, int e_begin, int e_end)
{
    const int S  = gridDim.x * blockDim.x;
    const int e0 = e_begin + blockIdx.x * blockDim.x + threadIdx.x;

    int                rows[8];
    unsigned long long pks[8];
    bool               ok[8];
#pragma unroll
    for (int i = 0; i < 8; i++) {
        const int e = e0 + i * S;
        ok[i] = (e < e_end);
        if (ok[i]) {
            rows[i] = erow[e];
            pks[i]  = ((unsigned long long)__float_as_uint(eval_[e]) << 32)
                    | (unsigned int)ecol[e];
        }
    }
    int ranks[8];
#pragma unroll
    for (int i = 0; i < 8; i++)
        if (ok[i]) ranks[i] = atomicAdd(&g_cnt[rows[i]], 1);
#pragma unroll
    for (int i = 0; i < 8; i++)
        if (ok[i] && ranks[i] < BIN_CAP)
            g_pack[(size_t)rows[i] * BIN_CAP + ranks[i]] = pks[i];
}

// ===========================================================================
// Gather v9: fp16 xw (v6 layout: 16 lanes x uint4 per edge, 2 edges per warp
// half), accumulation via packed fma.rn.f32x2 (4 FFMA2 instead of 8 FFMA per
// lane-edge). ReLU fused.
// ===========================================================================
__global__ __launch_bounds__(256) void gather_kernel(float* __restrict__ out, int n_nodes)
{
    const int wid  = threadIdx.x >> 5;
    const int lane = threadIdx.x & 31;
    const int row  = blockIdx.x * 8 + wid;
    if (row >= n_nodes) return;

    int n = g_cnt[row];
    n = n < BIN_CAP ? n : BIN_CAP;

    const int half = lane >> 4;        // which edge of the pair
    const int hl   = lane & 15;        // 16 slots x 16B = 256B row

    unsigned long long acc2[4] = {0ULL, 0ULL, 0ULL, 0ULL};   // 8 fp32 in 4 f32x2

    const unsigned long long* pkb = g_pack + (unsigned)row * BIN_CAP;

    for (int j0 = 0; j0 < n; j0 += 32) {
        const int rem = n - j0;
        const int m   = rem < 32 ? rem : 32;
        unsigned long long pk = 0ULL;
        if (lane < m) pk = __ldcg(&pkb[j0 + lane]);

        int t = 0;
        for (; t + 8 <= m; t += 8) {
            uint4 hh[4];
            unsigned long long vv2[4];
#pragma unroll
            for (int u = 0; u < 4; u++) {
                const unsigned long long p = __shfl_sync(0xffffffffu, pk, t + 2 * u + half);
                const unsigned col = (unsigned)(p & 0xffffffffULL);
                const float v = __uint_as_float((unsigned)(p >> 32));
                vv2[u] = pack2(v, v);
                hh[u] = __ldcg(&g_xw_h[(size_t)col * 16 + hl]);
            }
#pragma unroll
            for (int u = 0; u < 4; u++) {
                const float2 f0 = __half22float2(*reinterpret_cast<const __half2*>(&hh[u].x));
                const float2 f1 = __half22float2(*reinterpret_cast<const __half2*>(&hh[u].y));
                const float2 f2 = __half22float2(*reinterpret_cast<const __half2*>(&hh[u].z));
                const float2 f3 = __half22float2(*reinterpret_cast<const __half2*>(&hh[u].w));
                fma2(acc2[0], vv2[u], pack2(f0.x, f0.y));
                fma2(acc2[1], vv2[u], pack2(f1.x, f1.y));
                fma2(acc2[2], vv2[u], pack2(f2.x, f2.y));
                fma2(acc2[3], vv2[u], pack2(f3.x, f3.y));
            }
        }
        for (; t < m; t += 2) {
            const int idx = t + half;
            unsigned long long p = 0ULL;
            if (idx < 32) p = __shfl_sync(0xffffffffu, pk, idx);
            if (idx >= m) p = 0ULL;
            const unsigned col = (unsigned)(p & 0xffffffffULL);
            const float v = __uint_as_float((unsigned)(p >> 32));
            const unsigned long long vv2 = pack2(v, v);
            const uint4 hh = __ldcg(&g_xw_h[(size_t)col * 16 + hl]);
            const float2 f0 = __half22float2(*reinterpret_cast<const __half2*>(&hh.x));
            const float2 f1 = __half22float2(*reinterpret_cast<const __half2*>(&hh.y));
            const float2 f2 = __half22float2(*reinterpret_cast<const __half2*>(&hh.z));
            const float2 f3 = __half22float2(*reinterpret_cast<const __half2*>(&hh.w));
            fma2(acc2[0], vv2, pack2(f0.x, f0.y));
            fma2(acc2[1], vv2, pack2(f1.x, f1.y));
            fma2(acc2[2], vv2, pack2(f2.x, f2.y));
            fma2(acc2[3], vv2, pack2(f3.x, f3.y));
        }
    }

    float acc[8];
    unpack2(acc2[0], acc[0], acc[1]);
    unpack2(acc2[1], acc[2], acc[3]);
    unpack2(acc2[2], acc[4], acc[5]);
    unpack2(acc2[3], acc[6], acc[7]);

    // combine the two halves: lane l (<16) += lane l+16, same columns
#pragma unroll
    for (int i = 0; i < 8; i++) {
        const float o = __shfl_down_sync(0xffffffffu, acc[i], 16);
        acc[i] += o;
    }

    if (half == 0) {
        float4 o0 = make_float4(fmaxf(acc[0], 0.f), fmaxf(acc[1], 0.f),
                                fmaxf(acc[2], 0.f), fmaxf(acc[3], 0.f));
        float4 o1 = make_float4(fmaxf(acc[4], 0.f), fmaxf(acc[5], 0.f),
                                fmaxf(acc[6], 0.f), fmaxf(acc[7], 0.f));
        float4* dst = reinterpret_cast<float4*>(out + (size_t)row * UNITS + hl * 8);
        __stcg(&dst[0], o0);
        __stcg(&dst[1], o1);
    }
}

// ===========================================================================
// kernel_launch: graph-capturable, allocation-free.
// ===========================================================================
extern "C" void kernel_launch(void* const* d_in, const int* in_sizes, int n_in,
                              void* d_out, int out_size)
{
    const float* x     = (const float*)d_in[0];
    const float* w     = (const float*)d_in[1];
    const int*   erow  = (const int*)  d_in[2];
    const int*   ecol  = (const int*)  d_in[3];
    const float* eval_ = (const float*)d_in[4];
    float*       out   = (float*)d_out;

    const int n_nodes = in_sizes[0] / D_IN;
    const int n_edges = in_sizes[2];

    static bool         init_done = false;
    static void*        cnt_ptr   = nullptr;
    static cudaStream_t s2;
    static cudaEvent_t  ev_fork, ev_gemm;
    const int gemm_smem = (128 + 128) * XS_STRIDE * (int)sizeof(__half);  // 69632 B
    if (!init_done) {
        cudaFuncSetAttribute(gemm_kernel,
                             cudaFuncAttributeMaxDynamicSharedMemorySize, gemm_smem);
        cudaGetSymbolAddress(&cnt_ptr, g_cnt);
        cudaStreamCreateWithFlags(&s2, cudaStreamNonBlocking);
        cudaEventCreateWithFlags(&ev_fork, cudaEventDisableTiming);
        cudaEventCreateWithFlags(&ev_gemm, cudaEventDisableTiming);
        init_done = true;
    }

    const int n_tiles   = (n_nodes + 63) / 64;
    const int gemm_grid = 296;

    // Fork: GEMM on s2 overlaps edge prep on stream 0.
    cudaEventRecord(ev_fork, 0);
    cudaStreamWaitEvent(s2, ev_fork, 0);
    gemm_kernel<<<gemm_grid, 256, gemm_smem, s2>>>(x, w, n_nodes, n_tiles);
    cudaEventRecord(ev_gemm, s2);

    // Edge prep on stream 0 (hist_fill split in 2 for profiling alignment).
    cudaMemsetAsync(cnt_ptr, 0, (size_t)n_nodes * sizeof(int), 0);
    const int e_half    = n_edges / 2;
    const int hf_blocks = (e_half + 256 * 8 - 1) / (256 * 8);
    hist_fill_kernel<<<hf_blocks, 256>>>(erow, ecol, eval_, 0, e_half);
    hist_fill_kernel<<<hf_blocks, 256>>>(erow, ecol, eval_, e_half, n_edges);

    // Join: gather needs bins (stream 0) and xw (s2).
    cudaStreamWaitEvent(0, ev_gemm, 0);
    gather_kernel<<<(n_nodes + 7) / 8, 256>>>(out, n_nodes);
}

// round 16
// speedup vs baseline: 2.5558x; 1.0324x over previous
#include <cuda_runtime.h>
#include <cuda_fp16.h>
#include <cstdint>

#define D_IN      128
#define UNITS     128
#define MAX_NODES 100000
#define MAX_EDGES 1600000
#define BIN_CAP   64          // fixed per-row bin capacity (P(deg>=64) ~ 1e-14)
#define XS_STRIDE 136         // halves; 272B row stride -> conflict-free ldmatrix

// ---- device scratch (no runtime allocation allowed) ----
__device__ uint4              g_xw_h[(size_t)MAX_NODES * 16];       // xw fp16, 128 halves/row
__device__ int                g_cnt[MAX_NODES];
__device__ unsigned long long g_pack[(size_t)MAX_NODES * BIN_CAP];  // (half2(v,v)<<32)|col
__device__ int                g_bsum[128];

// ---- f32x2 packed helpers ----
__device__ __forceinline__ unsigned long long pack2(float lo, float hi) {
    unsigned long long r;
    asm("mov.b64 %0, {%1, %2};" : "=l"(r) : "r"(__float_as_uint(lo)), "r"(__float_as_uint(hi)));
    return r;
}
__device__ __forceinline__ void unpack2(unsigned long long v, float& lo, float& hi) {
    unsigned int a, b;
    asm("mov.b64 {%0, %1}, %2;" : "=r"(a), "=r"(b) : "l"(v));
    lo = __uint_as_float(a);
    hi = __uint_as_float(b);
}
__device__ __forceinline__ void add2(unsigned long long& d, unsigned long long a) {
    asm("add.rn.f32x2 %0, %0, %1;" : "+l"(d) : "l"(a));
}
__device__ __forceinline__ void fma2(unsigned long long& d, unsigned long long a, unsigned long long b) {
    asm("fma.rn.f32x2 %0, %1, %2, %0;" : "+l"(d) : "l"(a), "l"(b));
}

// ---- tensor-core primitives ----
__device__ __forceinline__ unsigned smem_u32(const void* p) {
    return (unsigned)__cvta_generic_to_shared(p);
}
__device__ __forceinline__ void ldsm_x4(unsigned addr, unsigned& r0, unsigned& r1,
                                        unsigned& r2, unsigned& r3) {
    asm volatile("ldmatrix.sync.aligned.m8n8.x4.shared.b16 {%0,%1,%2,%3}, [%4];"
                 : "=r"(r0), "=r"(r1), "=r"(r2), "=r"(r3) : "r"(addr));
}
__device__ __forceinline__ void ldsm_x4_t(unsigned addr, unsigned& r0, unsigned& r1,
                                          unsigned& r2, unsigned& r3) {
    asm volatile("ldmatrix.sync.aligned.m8n8.x4.trans.shared.b16 {%0,%1,%2,%3}, [%4];"
                 : "=r"(r0), "=r"(r1), "=r"(r2), "=r"(r3) : "r"(addr));
}
__device__ __forceinline__ void mma_16816(float* c, unsigned a0, unsigned a1, unsigned a2,
                                          unsigned a3, unsigned b0, unsigned b1) {
    asm volatile("mma.sync.aligned.m16n8k16.row.col.f32.f16.f16.f32 "
                 "{%0,%1,%2,%3}, {%4,%5,%6,%7}, {%8,%9}, {%0,%1,%2,%3};"
                 : "+f"(c[0]), "+f"(c[1]), "+f"(c[2]), "+f"(c[3])
                 : "r"(a0), "r"(a1), "r"(a2), "r"(a3), "r"(b0), "r"(b1));
}

// ===========================================================================
// Persistent GEMM: xw = x @ w (fp16 HMMA), 64-row tiles, double-buffered x,
// w staged once per block. fp16 epilogue into g_xw_h.
// ===========================================================================
__global__ __launch_bounds__(256, 2) void gemm_kernel(
    const float* __restrict__ x, const float* __restrict__ w,
    int n_rows, int n_tiles)
{
    extern __shared__ __half smh[];
    __half* ws  = smh;                            // [128][XS_STRIDE]
    __half* xs0 = smh + 128 * XS_STRIDE;
    __half* xs1 = smh + (128 + 64) * XS_STRIDE;

    const int tid  = threadIdx.x;
    const int wid  = tid >> 5;
    const int lane = tid & 31;

    {
        const float4* w4 = reinterpret_cast<const float4*>(w);
#pragma unroll
        for (int i = 0; i < 16; i++) {
            const int flat = i * 256 + tid;
            const int k  = flat >> 5;
            const int n4 = flat & 31;
            const float4 wv = w4[flat];
            const __half2 h0 = __floats2half2_rn(wv.x, wv.y);
            const __half2 h1 = __floats2half2_rn(wv.z, wv.w);
            uint2 st;
            st.x = *reinterpret_cast<const unsigned*>(&h0);
            st.y = *reinterpret_cast<const unsigned*>(&h1);
            *reinterpret_cast<uint2*>(&ws[k * XS_STRIDE + n4 * 4]) = st;
        }
    }

    const int wr = wid >> 1;
    const int wc = wid & 1;
    const int r_base = wr * 16;
    const int c_base = wc * 64;
    const unsigned ws_b = smem_u32(ws);
    const int lrow = lane & 15;
    const int lhi  = lane >> 4;

    int tile = blockIdx.x;
    if (tile >= n_tiles) return;

    float4 pf[8];
    {
        const float4* x4 = reinterpret_cast<const float4*>(x + (size_t)tile * 64 * D_IN);
#pragma unroll
        for (int i = 0; i < 8; i++) {
            const int flat = i * 256 + tid;
            const int r    = flat >> 5;
            pf[i] = (tile * 64 + r < n_rows) ? x4[flat] : make_float4(0.f, 0.f, 0.f, 0.f);
        }
    }
    {
        __half* xs = xs0;
#pragma unroll
        for (int i = 0; i < 8; i++) {
            const int flat = i * 256 + tid;
            const int r  = flat >> 5;
            const int k4 = flat & 31;
            const __half2 h0 = __floats2half2_rn(pf[i].x, pf[i].y);
            const __half2 h1 = __floats2half2_rn(pf[i].z, pf[i].w);
            uint2 st;
            st.x = *reinterpret_cast<const unsigned*>(&h0);
            st.y = *reinterpret_cast<const unsigned*>(&h1);
            *reinterpret_cast<uint2*>(&xs[r * XS_STRIDE + k4 * 4]) = st;
        }
    }
    __syncthreads();

    int buf = 0;
    while (true) {
        const int next = tile + gridDim.x;
        const int row0 = tile * 64;

        if (next < n_tiles) {
            const float4* x4 = reinterpret_cast<const float4*>(x + (size_t)next * 64 * D_IN);
#pragma unroll
            for (int i = 0; i < 8; i++) {
                const int flat = i * 256 + tid;
                const int r    = flat >> 5;
                pf[i] = (next * 64 + r < n_rows) ? x4[flat] : make_float4(0.f, 0.f, 0.f, 0.f);
            }
        }

        float acc[8][4];
#pragma unroll
        for (int i = 0; i < 8; i++) { acc[i][0] = acc[i][1] = acc[i][2] = acc[i][3] = 0.f; }
        const unsigned xs_b = smem_u32(buf ? xs1 : xs0);
#pragma unroll
        for (int kt = 0; kt < 8; kt++) {
            const int kb = kt * 16;
            unsigned a0, a1, a2, a3;
            ldsm_x4(xs_b + ((r_base + lrow) * XS_STRIDE + kb + lhi * 8) * 2, a0, a1, a2, a3);
#pragma unroll
            for (int np = 0; np < 4; np++) {
                unsigned b0, b1, b2, b3;
                ldsm_x4_t(ws_b + ((kb + lrow) * XS_STRIDE + c_base + np * 16 + lhi * 8) * 2,
                          b0, b1, b2, b3);
                mma_16816(acc[2 * np],     a0, a1, a2, a3, b0, b1);
                mma_16816(acc[2 * np + 1], a0, a1, a2, a3, b2, b3);
            }
        }

        {
            __half* xw = reinterpret_cast<__half*>(g_xw_h);
            const int er = row0 + r_base + (lane >> 2);
            const int ec = c_base + (lane & 3) * 2;
#pragma unroll
            for (int nt = 0; nt < 8; nt++) {
                const int c = ec + nt * 8;
                if (er < n_rows) {
                    const __half2 h = __floats2half2_rn(acc[nt][0], acc[nt][1]);
                    *reinterpret_cast<unsigned*>(&xw[(size_t)er * UNITS + c]) =
                        *reinterpret_cast<const unsigned*>(&h);
                }
                if (er + 8 < n_rows) {
                    const __half2 h = __floats2half2_rn(acc[nt][2], acc[nt][3]);
                    *reinterpret_cast<unsigned*>(&xw[(size_t)(er + 8) * UNITS + c]) =
                        *reinterpret_cast<const unsigned*>(&h);
                }
            }
        }

        if (next >= n_tiles) break;

        {
            __half* xs = buf ? xs0 : xs1;
#pragma unroll
            for (int i = 0; i < 8; i++) {
                const int flat = i * 256 + tid;
                const int r  = flat >> 5;
                const int k4 = flat & 31;
                const __half2 h0 = __floats2half2_rn(pf[i].x, pf[i].y);
                const __half2 h1 = __floats2half2_rn(pf[i].z, pf[i].w);
                uint2 st;
                st.x = *reinterpret_cast<const unsigned*>(&h0);
                st.y = *reinterpret_cast<const unsigned*>(&h1);
                *reinterpret_cast<uint2*>(&xs[r * XS_STRIDE + k4 * 4]) = st;
            }
        }
        __syncthreads();
        buf ^= 1;
        tile = next;
    }
}

// ===========================================================================
// Fused histogram + bin fill: 8 independent edges per thread.
// val is pre-converted to a duplicated half2 in the pack's high 32 bits.
// ===========================================================================
__global__ __launch_bounds__(256) void hist_fill_kernel(
    const int* __restrict__ erow, const int* __restrict__ ecol,
    const float* __restrict__ eval_, int e_begin, int e_end)
{
    const int S  = gridDim.x * blockDim.x;
    const int e0 = e_begin + blockIdx.x * blockDim.x + threadIdx.x;

    int                rows[8];
    unsigned long long pks[8];
    bool               ok[8];
#pragma unroll
    for (int i = 0; i < 8; i++) {
        const int e = e0 + i * S;
        ok[i] = (e < e_end);
        if (ok[i]) {
            rows[i] = erow[e];
            const __half2 h2 = __float2half2_rn(eval_[e]);
            pks[i] = ((unsigned long long)(*reinterpret_cast<const unsigned*>(&h2)) << 32)
                   | (unsigned int)ecol[e];
        }
    }
    int ranks[8];
#pragma unroll
    for (int i = 0; i < 8; i++)
        if (ok[i]) ranks[i] = atomicAdd(&g_cnt[rows[i]], 1);
#pragma unroll
    for (int i = 0; i < 8; i++)
        if (ok[i] && ranks[i] < BIN_CAP)
            g_pack[(size_t)rows[i] * BIN_CAP + ranks[i]] = pks[i];
}

// ===========================================================================
// Gather v10: fp16 HFMA2 inner accumulation over depth-4 chains (groups of
// 8 edges, 4 per warp-half), fp32 fold per group. Zero per-edge conversions.
// ===========================================================================
__global__ __launch_bounds__(256) void gather_kernel(float* __restrict__ out, int n_nodes)
{
    const int wid  = threadIdx.x >> 5;
    const int lane = threadIdx.x & 31;
    const int row  = blockIdx.x * 8 + wid;
    if (row >= n_nodes) return;

    int n = g_cnt[row];
    n = n < BIN_CAP ? n : BIN_CAP;

    const int half = lane >> 4;        // which edge of each pair
    const int hl   = lane & 15;        // 16 slots x 16B = 256B row

    unsigned long long acc2[4] = {0ULL, 0ULL, 0ULL, 0ULL};   // 8 fp32 in 4 f32x2
    const __half2 hz = __float2half2_rn(0.f);

    const unsigned long long* pkb = g_pack + (unsigned)row * BIN_CAP;

    for (int j0 = 0; j0 < n; j0 += 32) {
        const int rem = n - j0;
        const int m   = rem < 32 ? rem : 32;
        unsigned long long pk = 0ULL;
        if (lane < m) pk = __ldcg(&pkb[j0 + lane]);

        int t = 0;
        // group of 8 edges: each half accumulates 4 in fp16, then folds to fp32
        for (; t + 8 <= m; t += 8) {
            uint4   hh[4];
            __half2 vh[4];
#pragma unroll
            for (int u = 0; u < 4; u++) {
                const unsigned long long p = __shfl_sync(0xffffffffu, pk, t + 2 * u + half);
                const unsigned col = (unsigned)(p & 0xffffffffULL);
                const unsigned vbits = (unsigned)(p >> 32);
                vh[u] = *reinterpret_cast<const __half2*>(&vbits);
                hh[u] = __ldcg(&g_xw_h[(size_t)col * 16 + hl]);
            }
            __half2 ha0 = hz, ha1 = hz, ha2 = hz, ha3 = hz;
#pragma unroll
            for (int u = 0; u < 4; u++) {
                ha0 = __hfma2(*reinterpret_cast<const __half2*>(&hh[u].x), vh[u], ha0);
                ha1 = __hfma2(*reinterpret_cast<const __half2*>(&hh[u].y), vh[u], ha1);
                ha2 = __hfma2(*reinterpret_cast<const __half2*>(&hh[u].z), vh[u], ha2);
                ha3 = __hfma2(*reinterpret_cast<const __half2*>(&hh[u].w), vh[u], ha3);
            }
            const float2 f0 = __half22float2(ha0);
            const float2 f1 = __half22float2(ha1);
            const float2 f2 = __half22float2(ha2);
            const float2 f3 = __half22float2(ha3);
            add2(acc2[0], pack2(f0.x, f0.y));
            add2(acc2[1], pack2(f1.x, f1.y));
            add2(acc2[2], pack2(f2.x, f2.y));
            add2(acc2[3], pack2(f3.x, f3.y));
        }
        // tail pairs: fp32 path (precision-safe, rare)
        for (; t < m; t += 2) {
            const int idx = t + half;
            unsigned long long p = 0ULL;
            if (idx < 32) p = __shfl_sync(0xffffffffu, pk, idx);
            if (idx >= m) p = 0ULL;
            const unsigned col = (unsigned)(p & 0xffffffffULL);
            const unsigned vbits = (unsigned)(p >> 32);
            const __half2 vh2 = *reinterpret_cast<const __half2*>(&vbits);
            const float v = __half2float(__low2half(vh2));
            const unsigned long long vv2 = pack2(v, v);
            const uint4 hh = __ldcg(&g_xw_h[(size_t)col * 16 + hl]);
            const float2 f0 = __half22float2(*reinterpret_cast<const __half2*>(&hh.x));
            const float2 f1 = __half22float2(*reinterpret_cast<const __half2*>(&hh.y));
            const float2 f2 = __half22float2(*reinterpret_cast<const __half2*>(&hh.z));
            const float2 f3 = __half22float2(*reinterpret_cast<const __half2*>(&hh.w));
            fma2(acc2[0], vv2, pack2(f0.x, f0.y));
            fma2(acc2[1], vv2, pack2(f1.x, f1.y));
            fma2(acc2[2], vv2, pack2(f2.x, f2.y));
            fma2(acc2[3], vv2, pack2(f3.x, f3.y));
        }
    }

    float acc[8];
    unpack2(acc2[0], acc[0], acc[1]);
    unpack2(acc2[1], acc[2], acc[3]);
    unpack2(acc2[2], acc[4], acc[5]);
    unpack2(acc2[3], acc[6], acc[7]);

    // combine the two halves: lane l (<16) += lane l+16, same columns
#pragma unroll
    for (int i = 0; i < 8; i++) {
        const float o = __shfl_down_sync(0xffffffffu, acc[i], 16);
        acc[i] += o;
    }

    if (half == 0) {
        float4 o0 = make_float4(fmaxf(acc[0], 0.f), fmaxf(acc[1], 0.f),
                                fmaxf(acc[2], 0.f), fmaxf(acc[3], 0.f));
        float4 o1 = make_float4(fmaxf(acc[4], 0.f), fmaxf(acc[5], 0.f),
                                fmaxf(acc[6], 0.f), fmaxf(acc[7], 0.f));
        float4* dst = reinterpret_cast<float4*>(out + (size_t)row * UNITS + hl * 8);
        __stcg(&dst[0], o0);
        __stcg(&dst[1], o1);
    }
}

// ===========================================================================
// kernel_launch: graph-capturable, allocation-free.
// ===========================================================================
extern "C" void kernel_launch(void* const* d_in, const int* in_sizes, int n_in,
                              void* d_out, int out_size)
{
    const float* x     = (const float*)d_in[0];
    const float* w     = (const float*)d_in[1];
    const int*   erow  = (const int*)  d_in[2];
    const int*   ecol  = (const int*)  d_in[3];
    const float* eval_ = (const float*)d_in[4];
    float*       out   = (float*)d_out;

    const int n_nodes = in_sizes[0] / D_IN;
    const int n_edges = in_sizes[2];

    static bool         init_done = false;
    static void*        cnt_ptr   = nullptr;
    static cudaStream_t s2;
    static cudaEvent_t  ev_fork, ev_gemm;
    const int gemm_smem = (128 + 128) * XS_STRIDE * (int)sizeof(__half);  // 69632 B
    if (!init_done) {
        cudaFuncSetAttribute(gemm_kernel,
                             cudaFuncAttributeMaxDynamicSharedMemorySize, gemm_smem);
        cudaGetSymbolAddress(&cnt_ptr, g_cnt);
        cudaStreamCreateWithFlags(&s2, cudaStreamNonBlocking);
        cudaEventCreateWithFlags(&ev_fork, cudaEventDisableTiming);
        cudaEventCreateWithFlags(&ev_gemm, cudaEventDisableTiming);
        init_done = true;
    }

    const int n_tiles   = (n_nodes + 63) / 64;
    const int gemm_grid = 296;

    // Fork: GEMM on s2 overlaps edge prep on stream 0.
    cudaEventRecord(ev_fork, 0);
    cudaStreamWaitEvent(s2, ev_fork, 0);
    gemm_kernel<<<gemm_grid, 256, gemm_smem, s2>>>(x, w, n_nodes, n_tiles);
    cudaEventRecord(ev_gemm, s2);

    // Edge prep on stream 0 (hist_fill split in 2 for profiling alignment).
    cudaMemsetAsync(cnt_ptr, 0, (size_t)n_nodes * sizeof(int), 0);
    const int e_half    = n_edges / 2;
    const int hf_blocks = (e_half + 256 * 8 - 1) / (256 * 8);
    hist_fill_kernel<<<hf_blocks, 256>>>(erow, ecol, eval_, 0, e_half);
    hist_fill_kernel<<<hf_blocks, 256>>>(erow, ecol, eval_, e_half, n_edges);

    // Join: gather needs bins (stream 0) and xw (s2).
    cudaStreamWaitEvent(0, ev_gemm, 0);
    gather_kernel<<<(n_nodes + 7) / 8, 256>>>(out, n_nodes);
}